// round 10
// baseline (speedup 1.0000x reference)
#include <cuda_runtime.h>
#include <cuda_bf16.h>
#include <cstdint>

#define N_TOK 4096
#define DMODEL 1024
#define NHEAD  16
#define HD     64
#define GK     1024

// ---------------- scratch (__device__ globals; no allocation allowed) -------
__device__ float g_Q[N_TOK * DMODEL];
__device__ float g_K[N_TOK * DMODEL];
__device__ float g_V[N_TOK * DMODEL];
__device__ float g_C[N_TOK * DMODEL];

__device__ __nv_bfloat16 g_xhi[N_TOK * DMODEL];
__device__ __nv_bfloat16 g_xlo[N_TOK * DMODEL];
__device__ __nv_bfloat16 g_chi[N_TOK * DMODEL];
__device__ __nv_bfloat16 g_clo[N_TOK * DMODEL];

__device__ __nv_bfloat16 g_wq_hi[DMODEL * DMODEL];
__device__ __nv_bfloat16 g_wq_lo[DMODEL * DMODEL];
__device__ __nv_bfloat16 g_wk_hi[DMODEL * DMODEL];
__device__ __nv_bfloat16 g_wk_lo[DMODEL * DMODEL];
__device__ __nv_bfloat16 g_wv_hi[DMODEL * DMODEL];
__device__ __nv_bfloat16 g_wv_lo[DMODEL * DMODEL];
__device__ __nv_bfloat16 g_wo_hi[DMODEL * DMODEL];
__device__ __nv_bfloat16 g_wo_lo[DMODEL * DMODEL];

// attention operands, head-major bf16
__device__ __nv_bfloat16 g_qh[NHEAD * N_TOK * HD];
__device__ __nv_bfloat16 g_ql[NHEAD * N_TOK * HD];
__device__ __nv_bfloat16 g_kh[NHEAD * N_TOK * HD];
__device__ __nv_bfloat16 g_kl[NHEAD * N_TOK * HD];
__device__ __nv_bfloat16 g_vth[NHEAD * HD * N_TOK];   // V^T: [h][dim][token]
__device__ __nv_bfloat16 g_vtl[NHEAD * HD * N_TOK];

// ---------------- helpers ----------------------------------------------------
__device__ __forceinline__ void mma16816(float* d, const uint32_t* a, const uint32_t* b)
{
    asm volatile(
        "mma.sync.aligned.m16n8k16.row.col.f32.bf16.bf16.f32 "
        "{%0,%1,%2,%3}, {%4,%5,%6,%7}, {%8,%9}, {%0,%1,%2,%3};\n"
        : "+f"(d[0]), "+f"(d[1]), "+f"(d[2]), "+f"(d[3])
        : "r"(a[0]), "r"(a[1]), "r"(a[2]), "r"(a[3]), "r"(b[0]), "r"(b[1]));
}
__device__ __forceinline__ uint32_t pack_bf16x2(float lo, float hi)
{
    uint32_t d;
    asm("cvt.rn.bf16x2.f32 %0, %1, %2;" : "=r"(d) : "f"(hi), "f"(lo));
    return d;
}
__device__ __forceinline__ float bf16_round(float v)
{
    return __bfloat162float(__float2bfloat16(v));
}
__device__ __forceinline__ float fast_exp2(float x)
{
    float r;
    asm("ex2.approx.ftz.f32 %0, %1;" : "=f"(r) : "f"(x));
    return r;
}
__device__ __forceinline__ uint32_t smem_u32(const void* p)
{
    uint32_t a;
    asm("{ .reg .u64 t; cvta.to.shared.u64 t, %1; cvt.u32.u64 %0, t; }" : "=r"(a) : "l"(p));
    return a;
}
#define CP_ASYNC16(dst, src) \
    asm volatile("cp.async.cg.shared.global [%0], [%1], 16;" :: "r"(dst), "l"(src) : "memory")
#define CP_COMMIT() asm volatile("cp.async.commit_group;" ::: "memory")
#define CP_WAIT(n)  asm volatile("cp.async.wait_group %0;" :: "n"(n) : "memory")

// ---------------- split conversions ------------------------------------------
__global__ void __launch_bounds__(256) split_bf16(const float* __restrict__ src,
                                                  __nv_bfloat16* __restrict__ hi,
                                                  __nv_bfloat16* __restrict__ lo)
{
    int idx = blockIdx.x * 256 + threadIdx.x;
    int i4 = idx * 4;
    float4 v = *(const float4*)(src + i4);
    float h0 = bf16_round(v.x), h1 = bf16_round(v.y);
    float h2 = bf16_round(v.z), h3 = bf16_round(v.w);
    uint2 hv, lv;
    hv.x = pack_bf16x2(h0, h1);
    hv.y = pack_bf16x2(h2, h3);
    lv.x = pack_bf16x2(v.x - h0, v.y - h1);
    lv.y = pack_bf16x2(v.z - h2, v.w - h3);
    *(uint2*)(hi + i4) = hv;
    *(uint2*)(lo + i4) = lv;
}

// W [K,N] fp32 -> Wt hi/lo [N,K] bf16 (transposed split)
__global__ void __launch_bounds__(256) splitT_bf16(const float* __restrict__ W,
                                                   __nv_bfloat16* __restrict__ Thi,
                                                   __nv_bfloat16* __restrict__ Tlo)
{
    __shared__ float t[32][33];
    const int bk = blockIdx.x * 32;
    const int bn = blockIdx.y * 32;
    const int x = threadIdx.x;
    const int y = threadIdx.y;
#pragma unroll
    for (int r = 0; r < 32; r += 8)
        t[y + r][x] = W[(size_t)(bk + y + r) * DMODEL + bn + x];
    __syncthreads();
#pragma unroll
    for (int r = 0; r < 32; r += 8) {
        float v = t[x][y + r];
        float h = bf16_round(v);
        size_t o = (size_t)(bn + y + r) * GK + bk + x;
        Thi[o] = __float2bfloat16(h);
        Tlo[o] = __float2bfloat16(v - h);
    }
}

// [tok][h*64+d] fp32 -> head-major bf16 hi/lo [h][tok][64], scaled
__global__ void __launch_bounds__(256) split_head(const float* __restrict__ src,
                                                  __nv_bfloat16* __restrict__ hi,
                                                  __nv_bfloat16* __restrict__ lo,
                                                  float scale)
{
    int idx = blockIdx.x * 256 + threadIdx.x;
    int i4 = idx * 4;
    int tok = i4 >> 10;
    int c = i4 & 1023;
    int h = c >> 6;
    int d = c & 63;
    float4 v = *(const float4*)(src + i4);
    v.x *= scale; v.y *= scale; v.z *= scale; v.w *= scale;
    float h0 = bf16_round(v.x), h1 = bf16_round(v.y);
    float h2 = bf16_round(v.z), h3 = bf16_round(v.w);
    size_t off = ((size_t)h * N_TOK + tok) * HD + d;
    uint2 hv, lv;
    hv.x = pack_bf16x2(h0, h1);
    hv.y = pack_bf16x2(h2, h3);
    lv.x = pack_bf16x2(v.x - h0, v.y - h1);
    lv.y = pack_bf16x2(v.z - h2, v.w - h3);
    *(uint2*)(hi + off) = hv;
    *(uint2*)(lo + off) = lv;
}

// V [tok][h*64+d] fp32 -> V^T bf16 hi/lo [h][d][tok]
__global__ void __launch_bounds__(256) split_vT(const float* __restrict__ V,
                                                __nv_bfloat16* __restrict__ th,
                                                __nv_bfloat16* __restrict__ tl)
{
    __shared__ float s[64][68];   // 272B row stride: float4-aligned rows
    const int h = blockIdx.y;
    const int tok0 = blockIdx.x * 64;
    const int t = threadIdx.x;
#pragma unroll
    for (int i = 0; i < 4; i++) {
        int f = i * 256 + t;
        int r = f >> 4;
        int c4 = (f & 15) * 4;
        *(float4*)&s[r][c4] = *(const float4*)(V + (size_t)(tok0 + r) * DMODEL + h * HD + c4);
    }
    __syncthreads();
#pragma unroll
    for (int i = 0; i < 4; i++) {
        int f = i * 256 + t;
        int d = f >> 4;
        int tk4 = (f & 15) * 4;
        float v0 = s[tk4 + 0][d], v1 = s[tk4 + 1][d];
        float v2 = s[tk4 + 2][d], v3 = s[tk4 + 3][d];
        float h0 = bf16_round(v0), h1 = bf16_round(v1);
        float h2 = bf16_round(v2), h3 = bf16_round(v3);
        size_t off = ((size_t)(h * HD + d)) * N_TOK + tok0 + tk4;
        uint2 hv, lv;
        hv.x = pack_bf16x2(h0, h1);
        hv.y = pack_bf16x2(h2, h3);
        lv.x = pack_bf16x2(v0 - h0, v1 - h1);
        lv.y = pack_bf16x2(v2 - h2, v3 - h3);
        *(uint2*)(th + off) = hv;
        *(uint2*)(tl + off) = lv;
    }
}

// ---------------- mma.sync bf16 GEMM, cp.async double-buffered ---------------
#define RSTRIDE 80
#define TILE_SM (128 * RSTRIDE)            // 10240
#define GSTAGE  (4 * TILE_SM)              // 40960 per stage
#define GSMEM   (2 * GSTAGE)               // 81920

__global__ void __launch_bounds__(256) gemm_mma(
    const __nv_bfloat16* __restrict__ Ahi, const __nv_bfloat16* __restrict__ Alo,
    const __nv_bfloat16* __restrict__ Bhi, const __nv_bfloat16* __restrict__ Blo,
    const float* __restrict__ bias,
    float* __restrict__ C)
{
    extern __shared__ __align__(16) char dsm[];
    const uint32_t sb = smem_u32(dsm);

    const int t = threadIdx.x;
    const int lane = t & 31;
    const int wid = t >> 5;
    const int warp_m = wid & 1;
    const int warp_n = wid >> 1;
    const int bm = blockIdx.y * 128;
    const int bn = blockIdx.x * 128;

    const int qr = lane >> 2;
    const int qk4 = (lane & 3) * 4;

    float acc[4][4][4];
#pragma unroll
    for (int i = 0; i < 4; i++)
#pragma unroll
        for (int j = 0; j < 4; j++)
#pragma unroll
            for (int v = 0; v < 4; v++) acc[i][j][v] = 0.0f;

    const int lrow = t >> 2;
    const int lc = t & 3;

    // cp.async loader for one 32-K chunk into stage s
    auto issue = [&](int kci, int s) {
        const int kc = kci * 32;
        const uint32_t base = sb + s * GSTAGE;
#pragma unroll
        for (int i = 0; i < 2; i++) {
            const int row = lrow + i * 64;
            const uint32_t so = base + (uint32_t)row * RSTRIDE + (uint32_t)lc * 16;
            const size_t ga = (size_t)(bm + row) * GK + kc + lc * 8;
            const size_t gb = (size_t)(bn + row) * GK + kc + lc * 8;
            CP_ASYNC16(so,               Ahi + ga);
            CP_ASYNC16(so + TILE_SM,     Alo + ga);
            CP_ASYNC16(so + 2 * TILE_SM, Bhi + gb);
            CP_ASYNC16(so + 3 * TILE_SM, Blo + gb);
        }
        CP_COMMIT();
    };

    constexpr int NCHUNK = GK / 32;   // 32
    issue(0, 0);

    for (int kci = 0; kci < NCHUNK; kci++) {
        const int s = kci & 1;
        if (kci + 1 < NCHUNK) {
            issue(kci + 1, s ^ 1);
            CP_WAIT(1);
        } else {
            CP_WAIT(0);
        }
        __syncthreads();

        const char* sAhi = dsm + s * GSTAGE;
        const char* sAlo = sAhi + TILE_SM;
        const char* sBhi = sAhi + 2 * TILE_SM;
        const char* sBlo = sAhi + 3 * TILE_SM;

#pragma unroll
        for (int k16 = 0; k16 < 2; k16++) {
            const int kb = k16 * 32;
            uint32_t bh[4][2], bl[4][2];
#pragma unroll
            for (int na = 0; na < 4; na++) {
                const uint32_t nb = (uint32_t)(warp_n * 32 + na * 8 + qr) * RSTRIDE + kb + qk4;
                bh[na][0] = *(const uint32_t*)(sBhi + nb);
                bh[na][1] = *(const uint32_t*)(sBhi + nb + 16);
                bl[na][0] = *(const uint32_t*)(sBlo + nb);
                bl[na][1] = *(const uint32_t*)(sBlo + nb + 16);
            }
#pragma unroll
            for (int ma = 0; ma < 4; ma++) {
                const uint32_t ab = (uint32_t)(warp_m * 64 + ma * 16 + qr) * RSTRIDE + kb + qk4;
                uint32_t ah[4], al[4];
                ah[0] = *(const uint32_t*)(sAhi + ab);
                ah[1] = *(const uint32_t*)(sAhi + ab + 8 * RSTRIDE);
                ah[2] = *(const uint32_t*)(sAhi + ab + 16);
                ah[3] = *(const uint32_t*)(sAhi + ab + 8 * RSTRIDE + 16);
                al[0] = *(const uint32_t*)(sAlo + ab);
                al[1] = *(const uint32_t*)(sAlo + ab + 8 * RSTRIDE);
                al[2] = *(const uint32_t*)(sAlo + ab + 16);
                al[3] = *(const uint32_t*)(sAlo + ab + 8 * RSTRIDE + 16);
#pragma unroll
                for (int na = 0; na < 4; na++) mma16816(acc[ma][na], ah, bh[na]);
#pragma unroll
                for (int na = 0; na < 4; na++) mma16816(acc[ma][na], ah, bl[na]);
#pragma unroll
                for (int na = 0; na < 4; na++) mma16816(acc[ma][na], al, bh[na]);
            }
        }
        __syncthreads();   // readers done before this stage is refilled
    }

#pragma unroll
    for (int ma = 0; ma < 4; ma++) {
        const int row0 = bm + warp_m * 64 + ma * 16 + qr;
#pragma unroll
        for (int na = 0; na < 4; na++) {
            const int col = bn + warp_n * 32 + na * 8 + (lane & 3) * 2;
            float b0 = 0.f, b1 = 0.f;
            if (bias) { b0 = bias[col]; b1 = bias[col + 1]; }
            float2 o0, o1;
            o0.x = acc[ma][na][0] + b0;
            o0.y = acc[ma][na][1] + b1;
            o1.x = acc[ma][na][2] + b0;
            o1.y = acc[ma][na][3] + b1;
            *(float2*)(C + (size_t)row0 * DMODEL + col) = o0;
            *(float2*)(C + (size_t)(row0 + 8) * DMODEL + col) = o1;
        }
    }
}

// ---------------- tensor-core causal flash attention, cp.async pipelined -----
#define ASTRIDE 144
#define ATILE   (64 * ASTRIDE)             // 9216
#define ASTAGE  (4 * ATILE)                // 36864
#define ASMEM   (2 * ASTAGE)               // 73728

__global__ void __launch_bounds__(256) flash_mma(
    const __nv_bfloat16* __restrict__ qh, const __nv_bfloat16* __restrict__ ql,
    const __nv_bfloat16* __restrict__ kh, const __nv_bfloat16* __restrict__ kl,
    const __nv_bfloat16* __restrict__ vth, const __nv_bfloat16* __restrict__ vtl,
    float* __restrict__ C)
{
    extern __shared__ __align__(16) char dsm[];
    const uint32_t sb = smem_u32(dsm);

    const int t = threadIdx.x;
    const int lane = t & 31;
    const int w = t >> 5;
    const int qb = 31 - blockIdx.x;        // heavy CTAs first
    const int h = blockIdx.y;
    const int qr = lane >> 2;
    const int qc = lane & 3;
    const int r0 = qb * 128 + w * 16 + qr;
    const int row_max = qb * 128 + w * 16 + 15;

    // cp.async loader for key block kb into stage s
    auto issue = [&](int kb, int s) {
        const uint32_t base = sb + s * ASTAGE;
        const size_t kgo = ((size_t)h * N_TOK + kb * 64) * HD;
#pragma unroll
        for (int i = 0; i < 2; i++) {
            const int f = i * 256 + t;           // 0..511
            const int row = f >> 3;
            const int c = f & 7;
            const uint32_t so = base + (uint32_t)row * ASTRIDE + (uint32_t)c * 16;
            CP_ASYNC16(so,             kh + kgo + (size_t)row * HD + c * 8);
            CP_ASYNC16(so + ATILE,     kl + kgo + (size_t)row * HD + c * 8);
            const size_t vgo = ((size_t)(h * HD + row)) * N_TOK + kb * 64 + c * 8;
            CP_ASYNC16(so + 2 * ATILE, vth + vgo);
            CP_ASYNC16(so + 3 * ATILE, vtl + vgo);
        }
        CP_COMMIT();
    };

    // Q fragments (hi/lo), loaded once
    uint32_t qfh[4][4], qfl[4][4];
    {
        const size_t base = ((size_t)h * N_TOK + r0) * HD;
#pragma unroll
        for (int ks = 0; ks < 4; ks++) {
            const int d0 = ks * 16 + 2 * qc;
            qfh[ks][0] = *(const uint32_t*)(qh + base + d0);
            qfh[ks][1] = *(const uint32_t*)(qh + base + 8 * HD + d0);
            qfh[ks][2] = *(const uint32_t*)(qh + base + d0 + 8);
            qfh[ks][3] = *(const uint32_t*)(qh + base + 8 * HD + d0 + 8);
            qfl[ks][0] = *(const uint32_t*)(ql + base + d0);
            qfl[ks][1] = *(const uint32_t*)(ql + base + 8 * HD + d0);
            qfl[ks][2] = *(const uint32_t*)(ql + base + d0 + 8);
            qfl[ks][3] = *(const uint32_t*)(ql + base + 8 * HD + d0 + 8);
        }
    }

    float o_[8][4];
#pragma unroll
    for (int na = 0; na < 8; na++)
#pragma unroll
        for (int j = 0; j < 4; j++) o_[na][j] = 0.0f;
    float m_[2] = {-1e30f, -1e30f};
    float l_[2] = {0.0f, 0.0f};

    const int kb_max = 2 * qb + 1;
    issue(0, 0);

    for (int kb = 0; kb <= kb_max; kb++) {
        const int s = kb & 1;
        if (kb < kb_max) {
            issue(kb + 1, s ^ 1);
            CP_WAIT(1);
        } else {
            CP_WAIT(0);
        }
        __syncthreads();

        const char* sKh = dsm + s * ASTAGE;
        const char* sKl = sKh + ATILE;
        const char* sVh = sKh + 2 * ATILE;
        const char* sVl = sKh + 3 * ATILE;

        if (kb * 64 <= row_max) {
            // --- S = Q K^T (3 passes) ---
            float s_[8][4];
#pragma unroll
            for (int na = 0; na < 8; na++)
#pragma unroll
                for (int j = 0; j < 4; j++) s_[na][j] = 0.0f;

#pragma unroll
            for (int ks = 0; ks < 4; ks++) {
                uint32_t bh[8][2], bl[8][2];
#pragma unroll
                for (int na = 0; na < 8; na++) {
                    const uint32_t a = (uint32_t)(na * 8 + qr) * ASTRIDE + ks * 32 + qc * 4;
                    bh[na][0] = *(const uint32_t*)(sKh + a);
                    bh[na][1] = *(const uint32_t*)(sKh + a + 16);
                    bl[na][0] = *(const uint32_t*)(sKl + a);
                    bl[na][1] = *(const uint32_t*)(sKl + a + 16);
                }
#pragma unroll
                for (int na = 0; na < 8; na++) mma16816(s_[na], qfh[ks], bh[na]);
#pragma unroll
                for (int na = 0; na < 8; na++) mma16816(s_[na], qfl[ks], bh[na]);
#pragma unroll
                for (int na = 0; na < 8; na++) mma16816(s_[na], qfh[ks], bl[na]);
            }

            // --- causal mask (diagonal blocks only) ---
            if (kb >= 2 * qb) {
#pragma unroll
                for (int na = 0; na < 8; na++) {
                    const int key0 = kb * 64 + na * 8 + 2 * qc;
                    if (key0 > r0)     s_[na][0] = -1e30f;
                    if (key0 + 1 > r0) s_[na][1] = -1e30f;
                    if (key0 > r0 + 8)     s_[na][2] = -1e30f;
                    if (key0 + 1 > r0 + 8) s_[na][3] = -1e30f;
                }
            }

            // --- online softmax (log2 domain) ---
            float corr[2];
#pragma unroll
            for (int r = 0; r < 2; r++) {
                float mx = -1e30f;
#pragma unroll
                for (int na = 0; na < 8; na++) {
                    mx = fmaxf(mx, s_[na][2 * r]);
                    mx = fmaxf(mx, s_[na][2 * r + 1]);
                }
                mx = fmaxf(mx, __shfl_xor_sync(0xffffffffu, mx, 1));
                mx = fmaxf(mx, __shfl_xor_sync(0xffffffffu, mx, 2));
                const float m_new = fmaxf(m_[r], mx);
                corr[r] = fast_exp2(m_[r] - m_new);
                m_[r] = m_new;
                float psum = 0.0f;
#pragma unroll
                for (int na = 0; na < 8; na++) {
                    float p0 = fast_exp2(s_[na][2 * r] - m_new);
                    float p1 = fast_exp2(s_[na][2 * r + 1] - m_new);
                    s_[na][2 * r] = p0;
                    s_[na][2 * r + 1] = p1;
                    psum += p0 + p1;
                }
                l_[r] = l_[r] * corr[r] + psum;
            }
#pragma unroll
            for (int na = 0; na < 8; na++) {
                o_[na][0] *= corr[0];
                o_[na][1] *= corr[0];
                o_[na][2] *= corr[1];
                o_[na][3] *= corr[1];
            }

            // --- P fragments (hi/lo), register-direct from S atoms ---
            uint32_t pah[4][4], pal[4][4];
#pragma unroll
            for (int ka = 0; ka < 4; ka++) {
                const float* pA = s_[2 * ka];
                const float* pB = s_[2 * ka + 1];
                float hA0 = bf16_round(pA[0]), hA1 = bf16_round(pA[1]);
                float hA2 = bf16_round(pA[2]), hA3 = bf16_round(pA[3]);
                float hB0 = bf16_round(pB[0]), hB1 = bf16_round(pB[1]);
                float hB2 = bf16_round(pB[2]), hB3 = bf16_round(pB[3]);
                pah[ka][0] = pack_bf16x2(hA0, hA1);
                pah[ka][1] = pack_bf16x2(hA2, hA3);
                pah[ka][2] = pack_bf16x2(hB0, hB1);
                pah[ka][3] = pack_bf16x2(hB2, hB3);
                pal[ka][0] = pack_bf16x2(pA[0] - hA0, pA[1] - hA1);
                pal[ka][1] = pack_bf16x2(pA[2] - hA2, pA[3] - hA3);
                pal[ka][2] = pack_bf16x2(pB[0] - hB0, pB[1] - hB1);
                pal[ka][3] = pack_bf16x2(pB[2] - hB2, pB[3] - hB3);
            }

            // --- O += P V (3 passes) ---
#pragma unroll
            for (int ka = 0; ka < 4; ka++) {
                uint32_t vh[8][2], vl[8][2];
#pragma unroll
                for (int na = 0; na < 8; na++) {
                    const uint32_t a = (uint32_t)(na * 8 + qr) * ASTRIDE + ka * 32 + qc * 4;
                    vh[na][0] = *(const uint32_t*)(sVh + a);
                    vh[na][1] = *(const uint32_t*)(sVh + a + 16);
                    vl[na][0] = *(const uint32_t*)(sVl + a);
                    vl[na][1] = *(const uint32_t*)(sVl + a + 16);
                }
#pragma unroll
                for (int na = 0; na < 8; na++) mma16816(o_[na], pah[ka], vh[na]);
#pragma unroll
                for (int na = 0; na < 8; na++) mma16816(o_[na], pal[ka], vh[na]);
#pragma unroll
                for (int na = 0; na < 8; na++) mma16816(o_[na], pah[ka], vl[na]);
            }
        }
        __syncthreads();   // stage free before refill next iteration
    }

    // finalize: quad-reduce l, normalize, store
    float l0 = l_[0];
    l0 += __shfl_xor_sync(0xffffffffu, l0, 1);
    l0 += __shfl_xor_sync(0xffffffffu, l0, 2);
    float l1 = l_[1];
    l1 += __shfl_xor_sync(0xffffffffu, l1, 1);
    l1 += __shfl_xor_sync(0xffffffffu, l1, 2);
    const float inv0 = 1.0f / l0;
    const float inv1 = 1.0f / l1;

#pragma unroll
    for (int na = 0; na < 8; na++) {
        const int col = h * HD + na * 8 + 2 * qc;
        float2 w0, w1;
        w0.x = o_[na][0] * inv0;
        w0.y = o_[na][1] * inv0;
        w1.x = o_[na][2] * inv1;
        w1.y = o_[na][3] * inv1;
        *(float2*)(C + (size_t)r0 * DMODEL + col) = w0;
        *(float2*)(C + (size_t)(r0 + 8) * DMODEL + col) = w1;
    }
}

// ---------------------------------------------------------------------------
extern "C" void kernel_launch(void* const* d_in, const int* in_sizes, int n_in,
                              void* d_out, int out_size)
{
    const float* x   = (const float*)d_in[0];
    const float* W_q = (const float*)d_in[1];
    const float* W_k = (const float*)d_in[2];
    const float* W_v = (const float*)d_in[3];
    const float* W_o = (const float*)d_in[4];
    const float* b_o = (const float*)d_in[5];
    float* out = (float*)d_out;

    float *qp, *kp, *vp, *cp;
    cudaGetSymbolAddress((void**)&qp, g_Q);
    cudaGetSymbolAddress((void**)&kp, g_K);
    cudaGetSymbolAddress((void**)&vp, g_V);
    cudaGetSymbolAddress((void**)&cp, g_C);

    __nv_bfloat16 *xhi, *xlo, *chi, *clo;
    __nv_bfloat16 *wqh, *wql, *wkh, *wkl, *wvh, *wvl, *woh, *wol;
    __nv_bfloat16 *aqh, *aql, *akh, *akl, *avh, *avl;
    cudaGetSymbolAddress((void**)&xhi, g_xhi);
    cudaGetSymbolAddress((void**)&xlo, g_xlo);
    cudaGetSymbolAddress((void**)&chi, g_chi);
    cudaGetSymbolAddress((void**)&clo, g_clo);
    cudaGetSymbolAddress((void**)&wqh, g_wq_hi);
    cudaGetSymbolAddress((void**)&wql, g_wq_lo);
    cudaGetSymbolAddress((void**)&wkh, g_wk_hi);
    cudaGetSymbolAddress((void**)&wkl, g_wk_lo);
    cudaGetSymbolAddress((void**)&wvh, g_wv_hi);
    cudaGetSymbolAddress((void**)&wvl, g_wv_lo);
    cudaGetSymbolAddress((void**)&woh, g_wo_hi);
    cudaGetSymbolAddress((void**)&wol, g_wo_lo);
    cudaGetSymbolAddress((void**)&aqh, g_qh);
    cudaGetSymbolAddress((void**)&aql, g_ql);
    cudaGetSymbolAddress((void**)&akh, g_kh);
    cudaGetSymbolAddress((void**)&akl, g_kl);
    cudaGetSymbolAddress((void**)&avh, g_vth);
    cudaGetSymbolAddress((void**)&avl, g_vtl);

    cudaFuncSetAttribute(gemm_mma, cudaFuncAttributeMaxDynamicSharedMemorySize, GSMEM);
    cudaFuncSetAttribute(flash_mma, cudaFuncAttributeMaxDynamicSharedMemorySize, ASMEM);

    // split x + weights
    split_bf16<<<(N_TOK * DMODEL) / (256 * 4), 256>>>(x, xhi, xlo);
    dim3 tgrid(DMODEL / 32, DMODEL / 32);
    dim3 tblock(32, 8);
    splitT_bf16<<<tgrid, tblock>>>(W_q, wqh, wql);
    splitT_bf16<<<tgrid, tblock>>>(W_k, wkh, wkl);
    splitT_bf16<<<tgrid, tblock>>>(W_v, wvh, wvl);
    splitT_bf16<<<tgrid, tblock>>>(W_o, woh, wol);

    // projections (tensor cores, pipelined)
    dim3 ggrid(DMODEL / 128, N_TOK / 128);
    gemm_mma<<<ggrid, 256, GSMEM>>>(xhi, xlo, wqh, wql, nullptr, qp);
    gemm_mma<<<ggrid, 256, GSMEM>>>(xhi, xlo, wkh, wkl, nullptr, kp);
    gemm_mma<<<ggrid, 256, GSMEM>>>(xhi, xlo, wvh, wvl, nullptr, vp);

    // attention operand prep (scale = 1/sqrt(64) * log2(e), folded into Q)
    const float qscale = 0.125f * 1.4426950408889634f;
    split_head<<<(N_TOK * DMODEL) / (256 * 4), 256>>>(qp, aqh, aql, qscale);
    split_head<<<(N_TOK * DMODEL) / (256 * 4), 256>>>(kp, akh, akl, 1.0f);
    dim3 vgrid(N_TOK / 64, NHEAD);
    split_vT<<<vgrid, 256>>>(vp, avh, avl);

    // tensor-core causal flash attention (pipelined)
    dim3 agrid(N_TOK / 128, NHEAD);
    flash_mma<<<agrid, 256, ASMEM>>>(aqh, aql, akh, akl, avh, avl, cp);

    // output projection
    split_bf16<<<(N_TOK * DMODEL) / (256 * 4), 256>>>(cp, chi, clo);
    gemm_mma<<<ggrid, 256, GSMEM>>>(chi, clo, woh, wol, b_o, out);
}

// round 11
// speedup vs baseline: 3.3642x; 3.3642x over previous
#include <cuda_runtime.h>
#include <cuda_fp16.h>
#include <cstdint>

#define N_TOK 4096
#define DMODEL 1024
#define NHEAD  16
#define HD     64
#define GK     1024

// ---------------- scratch (__device__ globals; no allocation allowed) -------
__device__ __half g_x16[N_TOK * DMODEL];
__device__ __half g_c16[N_TOK * DMODEL];
__device__ __half g_wq16[DMODEL * DMODEL];   // transposed [N][K]
__device__ __half g_wk16[DMODEL * DMODEL];
__device__ __half g_wv16[DMODEL * DMODEL];
__device__ __half g_wo16[DMODEL * DMODEL];
__device__ __half g_q16[NHEAD * N_TOK * HD]; // head-major, pre-scaled
__device__ __half g_k16[NHEAD * N_TOK * HD];
__device__ __half g_vt16[DMODEL * N_TOK];    // V^T flat: [col][tok]

// ---------------- helpers ----------------------------------------------------
__device__ __forceinline__ void mma16816(float* d, const uint32_t* a, const uint32_t* b)
{
    asm volatile(
        "mma.sync.aligned.m16n8k16.row.col.f32.f16.f16.f32 "
        "{%0,%1,%2,%3}, {%4,%5,%6,%7}, {%8,%9}, {%0,%1,%2,%3};\n"
        : "+f"(d[0]), "+f"(d[1]), "+f"(d[2]), "+f"(d[3])
        : "r"(a[0]), "r"(a[1]), "r"(a[2]), "r"(a[3]), "r"(b[0]), "r"(b[1]));
}
__device__ __forceinline__ uint32_t pack_f16x2(float lo, float hi)
{
    uint32_t d;
    asm("cvt.rn.f16x2.f32 %0, %1, %2;" : "=r"(d) : "f"(hi), "f"(lo));
    return d;
}
__device__ __forceinline__ float fast_exp2(float x)
{
    float r;
    asm("ex2.approx.ftz.f32 %0, %1;" : "=f"(r) : "f"(x));
    return r;
}

// ---------------- conversion kernels -----------------------------------------
// x fp32 -> fp16 flat (8 elems/thread)
__global__ void __launch_bounds__(256) cvt_f16(const float* __restrict__ src,
                                               __half* __restrict__ dst)
{
    int i8 = (blockIdx.x * 256 + threadIdx.x) * 8;
    float4 a = *(const float4*)(src + i8);
    float4 b = *(const float4*)(src + i8 + 4);
    uint4 o;
    o.x = pack_f16x2(a.x, a.y);
    o.y = pack_f16x2(a.z, a.w);
    o.z = pack_f16x2(b.x, b.y);
    o.w = pack_f16x2(b.z, b.w);
    *(uint4*)(dst + i8) = o;
}

// W [K,N] fp32 -> Wt fp16 [N,K]
__global__ void __launch_bounds__(256) wT_f16(const float* __restrict__ W,
                                              __half* __restrict__ T)
{
    __shared__ float t[32][33];
    const int bk = blockIdx.x * 32;
    const int bn = blockIdx.y * 32;
    const int x = threadIdx.x;
    const int y = threadIdx.y;
#pragma unroll
    for (int r = 0; r < 32; r += 8)
        t[y + r][x] = W[(size_t)(bk + y + r) * DMODEL + bn + x];
    __syncthreads();
#pragma unroll
    for (int r = 0; r < 32; r += 8)
        T[(size_t)(bn + y + r) * GK + bk + x] = __float2half_rn(t[x][y + r]);
}

// ---------------- fp16 mma GEMM, register-prefetch pipelined -----------------
// C[M,N] = A[M,K] * B[N,K]^T. Tile 128x128, BK=32, 256 threads.
// MODE 0: fp32 out + bias. MODE 1: head-major fp16 out, scaled. MODE 2: V^T fp16 out.
#define RSTRIDE 80
#define TILE_SM (128 * RSTRIDE)

template <int MODE>
__global__ void __launch_bounds__(256) gemm_f16(
    const __half* __restrict__ A, const __half* __restrict__ B,
    const float* __restrict__ bias, float* __restrict__ Cf,
    __half* __restrict__ C16, float scale)
{
    __shared__ __align__(16) char sA[TILE_SM];
    __shared__ __align__(16) char sB[TILE_SM];

    const int t = threadIdx.x;
    const int lane = t & 31;
    const int wid = t >> 5;
    const int warp_m = wid & 1;
    const int warp_n = wid >> 1;
    const int bm = blockIdx.y * 128;
    const int bn = blockIdx.x * 128;

    const int qr = lane >> 2;
    const int qk4 = (lane & 3) * 4;
    const int lrow = t >> 2;
    const int lc = t & 3;

    float acc[4][4][4];
#pragma unroll
    for (int i = 0; i < 4; i++)
#pragma unroll
        for (int j = 0; j < 4; j++)
#pragma unroll
            for (int v = 0; v < 4; v++) acc[i][j][v] = 0.0f;

    uint4 pa[2], pb[2];
    auto gload = [&](int kci) {
        const int kc = kci * 32;
#pragma unroll
        for (int i = 0; i < 2; i++) {
            const int row = lrow + i * 64;
            pa[i] = *(const uint4*)(A + (size_t)(bm + row) * GK + kc + lc * 8);
            pb[i] = *(const uint4*)(B + (size_t)(bn + row) * GK + kc + lc * 8);
        }
    };

    constexpr int NCHUNK = GK / 32;
    gload(0);

    for (int kci = 0; kci < NCHUNK; kci++) {
        __syncthreads();   // readers of previous chunk done
#pragma unroll
        for (int i = 0; i < 2; i++) {
            const uint32_t so = (uint32_t)(lrow + i * 64) * RSTRIDE + (uint32_t)lc * 16;
            *(uint4*)(sA + so) = pa[i];
            *(uint4*)(sB + so) = pb[i];
        }
        __syncthreads();
        if (kci + 1 < NCHUNK) gload(kci + 1);   // LDG latency hidden by MMAs below

#pragma unroll
        for (int k16 = 0; k16 < 2; k16++) {
            const int kb = k16 * 32;
            uint32_t bf[4][2];
#pragma unroll
            for (int na = 0; na < 4; na++) {
                const uint32_t nb = (uint32_t)(warp_n * 32 + na * 8 + qr) * RSTRIDE + kb + qk4;
                bf[na][0] = *(const uint32_t*)(sB + nb);
                bf[na][1] = *(const uint32_t*)(sB + nb + 16);
            }
#pragma unroll
            for (int ma = 0; ma < 4; ma++) {
                const uint32_t ab = (uint32_t)(warp_m * 64 + ma * 16 + qr) * RSTRIDE + kb + qk4;
                uint32_t af[4];
                af[0] = *(const uint32_t*)(sA + ab);
                af[1] = *(const uint32_t*)(sA + ab + 8 * RSTRIDE);
                af[2] = *(const uint32_t*)(sA + ab + 16);
                af[3] = *(const uint32_t*)(sA + ab + 8 * RSTRIDE + 16);
#pragma unroll
                for (int na = 0; na < 4; na++) mma16816(acc[ma][na], af, bf[na]);
            }
        }
    }

    // epilogue
#pragma unroll
    for (int ma = 0; ma < 4; ma++) {
        const int row0 = bm + warp_m * 64 + ma * 16 + qr;
#pragma unroll
        for (int na = 0; na < 4; na++) {
            const int col = bn + warp_n * 32 + na * 8 + (lane & 3) * 2;
            if (MODE == 0) {
                float b0 = 0.f, b1 = 0.f;
                if (bias) { b0 = bias[col]; b1 = bias[col + 1]; }
                float2 o0, o1;
                o0.x = acc[ma][na][0] + b0;
                o0.y = acc[ma][na][1] + b1;
                o1.x = acc[ma][na][2] + b0;
                o1.y = acc[ma][na][3] + b1;
                *(float2*)(Cf + (size_t)row0 * DMODEL + col) = o0;
                *(float2*)(Cf + (size_t)(row0 + 8) * DMODEL + col) = o1;
            } else if (MODE == 1) {
                const int hh = col >> 6;
                const int d = col & 63;
                uint32_t p0 = pack_f16x2(acc[ma][na][0] * scale, acc[ma][na][1] * scale);
                uint32_t p1 = pack_f16x2(acc[ma][na][2] * scale, acc[ma][na][3] * scale);
                *(uint32_t*)(C16 + ((size_t)hh * N_TOK + row0) * HD + d) = p0;
                *(uint32_t*)(C16 + ((size_t)hh * N_TOK + row0 + 8) * HD + d) = p1;
            } else {
                // V^T: [col][tok]
                C16[(size_t)col * N_TOK + row0]           = __float2half_rn(acc[ma][na][0]);
                C16[(size_t)(col + 1) * N_TOK + row0]     = __float2half_rn(acc[ma][na][1]);
                C16[(size_t)col * N_TOK + row0 + 8]       = __float2half_rn(acc[ma][na][2]);
                C16[(size_t)(col + 1) * N_TOK + row0 + 8] = __float2half_rn(acc[ma][na][3]);
            }
        }
    }
}

// ---------------- fp16 tensor-core causal flash attention --------------------
// CTA = (128 queries, 1 head), 256 threads, warp owns 16 rows. Single-pass fp16.
#define ASTRIDE 144
#define ATILE   (64 * ASTRIDE)

__global__ void __launch_bounds__(256) flash_f16(
    const __half* __restrict__ q16, const __half* __restrict__ k16,
    const __half* __restrict__ vt16,
    __half* __restrict__ C16)
{
    __shared__ __align__(16) char sK[ATILE];
    __shared__ __align__(16) char sV[ATILE];

    const int t = threadIdx.x;
    const int lane = t & 31;
    const int w = t >> 5;
    const int qb = 31 - blockIdx.x;        // heavy CTAs first
    const int h = blockIdx.y;
    const int qr = lane >> 2;
    const int qc = lane & 3;
    const int r0 = qb * 128 + w * 16 + qr;
    const int row_max = qb * 128 + w * 16 + 15;

    // Q fragments, loaded once
    uint32_t qf[4][4];
    {
        const size_t base = ((size_t)h * N_TOK + r0) * HD;
#pragma unroll
        for (int ks = 0; ks < 4; ks++) {
            const int d0 = ks * 16 + 2 * qc;
            qf[ks][0] = *(const uint32_t*)(q16 + base + d0);
            qf[ks][1] = *(const uint32_t*)(q16 + base + 8 * HD + d0);
            qf[ks][2] = *(const uint32_t*)(q16 + base + d0 + 8);
            qf[ks][3] = *(const uint32_t*)(q16 + base + 8 * HD + d0 + 8);
        }
    }

    float o_[8][4];
#pragma unroll
    for (int na = 0; na < 8; na++)
#pragma unroll
        for (int j = 0; j < 4; j++) o_[na][j] = 0.0f;
    float m_[2] = {-1e30f, -1e30f};
    float l_[2] = {0.0f, 0.0f};

    const int kb_max = 2 * qb + 1;
    for (int kb = 0; kb <= kb_max; kb++) {
        __syncthreads();
        {
            const size_t kgo = ((size_t)h * N_TOK + kb * 64) * HD;
            const size_t vco = (size_t)(h * HD) * N_TOK + kb * 64;
#pragma unroll
            for (int i = 0; i < 2; i++) {
                const int f = i * 256 + t;          // 0..511
                const int row = f >> 3;
                const int c = f & 7;
                const uint32_t so = (uint32_t)row * ASTRIDE + (uint32_t)c * 16;
                *(uint4*)(sK + so) = *(const uint4*)(k16 + kgo + (size_t)row * HD + c * 8);
                *(uint4*)(sV + so) = *(const uint4*)(vt16 + vco + (size_t)row * N_TOK + c * 8);
            }
        }
        __syncthreads();

        if (kb * 64 <= row_max) {
            // --- S = Q K^T (single fp16 pass) ---
            float s_[8][4];
#pragma unroll
            for (int na = 0; na < 8; na++)
#pragma unroll
                for (int j = 0; j < 4; j++) s_[na][j] = 0.0f;

#pragma unroll
            for (int ks = 0; ks < 4; ks++) {
                uint32_t bf[8][2];
#pragma unroll
                for (int na = 0; na < 8; na++) {
                    const uint32_t a = (uint32_t)(na * 8 + qr) * ASTRIDE + ks * 32 + qc * 4;
                    bf[na][0] = *(const uint32_t*)(sK + a);
                    bf[na][1] = *(const uint32_t*)(sK + a + 16);
                }
#pragma unroll
                for (int na = 0; na < 8; na++) mma16816(s_[na], qf[ks], bf[na]);
            }

            // --- causal mask (diagonal blocks only) ---
            if (kb >= 2 * qb) {
#pragma unroll
                for (int na = 0; na < 8; na++) {
                    const int key0 = kb * 64 + na * 8 + 2 * qc;
                    if (key0 > r0)     s_[na][0] = -1e30f;
                    if (key0 + 1 > r0) s_[na][1] = -1e30f;
                    if (key0 > r0 + 8)     s_[na][2] = -1e30f;
                    if (key0 + 1 > r0 + 8) s_[na][3] = -1e30f;
                }
            }

            // --- online softmax (log2 domain; scale folded into Q) ---
            float corr[2];
#pragma unroll
            for (int r = 0; r < 2; r++) {
                float mx = -1e30f;
#pragma unroll
                for (int na = 0; na < 8; na++) {
                    mx = fmaxf(mx, s_[na][2 * r]);
                    mx = fmaxf(mx, s_[na][2 * r + 1]);
                }
                mx = fmaxf(mx, __shfl_xor_sync(0xffffffffu, mx, 1));
                mx = fmaxf(mx, __shfl_xor_sync(0xffffffffu, mx, 2));
                const float m_new = fmaxf(m_[r], mx);
                corr[r] = fast_exp2(m_[r] - m_new);
                m_[r] = m_new;
                float psum = 0.0f;
#pragma unroll
                for (int na = 0; na < 8; na++) {
                    float p0 = fast_exp2(s_[na][2 * r] - m_new);
                    float p1 = fast_exp2(s_[na][2 * r + 1] - m_new);
                    s_[na][2 * r] = p0;
                    s_[na][2 * r + 1] = p1;
                    psum += p0 + p1;
                }
                l_[r] = l_[r] * corr[r] + psum;
            }
#pragma unroll
            for (int na = 0; na < 8; na++) {
                o_[na][0] *= corr[0];
                o_[na][1] *= corr[0];
                o_[na][2] *= corr[1];
                o_[na][3] *= corr[1];
            }

            // --- P fragments (fp16), register-direct from S atoms ---
            uint32_t pa[4][4];
#pragma unroll
            for (int ka = 0; ka < 4; ka++) {
                const float* pA = s_[2 * ka];
                const float* pB = s_[2 * ka + 1];
                pa[ka][0] = pack_f16x2(pA[0], pA[1]);
                pa[ka][1] = pack_f16x2(pA[2], pA[3]);
                pa[ka][2] = pack_f16x2(pB[0], pB[1]);
                pa[ka][3] = pack_f16x2(pB[2], pB[3]);
            }

            // --- O += P V (single fp16 pass) ---
#pragma unroll
            for (int ka = 0; ka < 4; ka++) {
                uint32_t vf[8][2];
#pragma unroll
                for (int na = 0; na < 8; na++) {
                    const uint32_t a = (uint32_t)(na * 8 + qr) * ASTRIDE + ka * 32 + qc * 4;
                    vf[na][0] = *(const uint32_t*)(sV + a);
                    vf[na][1] = *(const uint32_t*)(sV + a + 16);
                }
#pragma unroll
                for (int na = 0; na < 8; na++) mma16816(o_[na], pa[ka], vf[na]);
            }
        }
    }

    // finalize: quad-reduce l, normalize, store ctx as fp16
    float l0 = l_[0];
    l0 += __shfl_xor_sync(0xffffffffu, l0, 1);
    l0 += __shfl_xor_sync(0xffffffffu, l0, 2);
    float l1 = l_[1];
    l1 += __shfl_xor_sync(0xffffffffu, l1, 1);
    l1 += __shfl_xor_sync(0xffffffffu, l1, 2);
    const float inv0 = 1.0f / l0;
    const float inv1 = 1.0f / l1;

#pragma unroll
    for (int na = 0; na < 8; na++) {
        const int col = h * HD + na * 8 + 2 * qc;
        uint32_t p0 = pack_f16x2(o_[na][0] * inv0, o_[na][1] * inv0);
        uint32_t p1 = pack_f16x2(o_[na][2] * inv1, o_[na][3] * inv1);
        *(uint32_t*)(C16 + (size_t)r0 * DMODEL + col) = p0;
        *(uint32_t*)(C16 + (size_t)(r0 + 8) * DMODEL + col) = p1;
    }
}

// ---------------------------------------------------------------------------
extern "C" void kernel_launch(void* const* d_in, const int* in_sizes, int n_in,
                              void* d_out, int out_size)
{
    const float* x   = (const float*)d_in[0];
    const float* W_q = (const float*)d_in[1];
    const float* W_k = (const float*)d_in[2];
    const float* W_v = (const float*)d_in[3];
    const float* W_o = (const float*)d_in[4];
    const float* b_o = (const float*)d_in[5];
    float* out = (float*)d_out;

    __half *x16, *c16, *wq, *wk, *wv, *wo, *q16, *k16, *vt16;
    cudaGetSymbolAddress((void**)&x16, g_x16);
    cudaGetSymbolAddress((void**)&c16, g_c16);
    cudaGetSymbolAddress((void**)&wq, g_wq16);
    cudaGetSymbolAddress((void**)&wk, g_wk16);
    cudaGetSymbolAddress((void**)&wv, g_wv16);
    cudaGetSymbolAddress((void**)&wo, g_wo16);
    cudaGetSymbolAddress((void**)&q16, g_q16);
    cudaGetSymbolAddress((void**)&k16, g_k16);
    cudaGetSymbolAddress((void**)&vt16, g_vt16);

    // convert inputs to fp16
    cvt_f16<<<(N_TOK * DMODEL) / (256 * 8), 256>>>(x, x16);
    dim3 tgrid(DMODEL / 32, DMODEL / 32);
    dim3 tblock(32, 8);
    wT_f16<<<tgrid, tblock>>>(W_q, wq);
    wT_f16<<<tgrid, tblock>>>(W_k, wk);
    wT_f16<<<tgrid, tblock>>>(W_v, wv);
    wT_f16<<<tgrid, tblock>>>(W_o, wo);

    // projections: epilogues emit attention operands directly
    const float qscale = 0.125f * 1.4426950408889634f;   // 1/sqrt(64) * log2(e)
    dim3 ggrid(DMODEL / 128, N_TOK / 128);   // (8, 32)
    gemm_f16<1><<<ggrid, 256>>>(x16, wq, nullptr, nullptr, q16, qscale);
    gemm_f16<1><<<ggrid, 256>>>(x16, wk, nullptr, nullptr, k16, 1.0f);
    gemm_f16<2><<<ggrid, 256>>>(x16, wv, nullptr, nullptr, vt16, 1.0f);

    // tensor-core causal flash attention (fp16 single-pass)
    dim3 agrid(N_TOK / 128, NHEAD);
    flash_f16<<<agrid, 256>>>(q16, k16, vt16, c16);

    // output projection: fp32 + bias to harness output
    gemm_f16<0><<<ggrid, 256>>>(c16, wo, b_o, out, nullptr, 1.0f);
}

// round 13
// speedup vs baseline: 3.4240x; 1.0178x over previous
#include <cuda_runtime.h>
#include <cuda_fp16.h>
#include <cstdint>

#define N_TOK 4096
#define DMODEL 1024
#define NHEAD  16
#define HD     64
#define GK     1024

// ---------------- scratch (__device__ globals; no allocation allowed) -------
__device__ __half g_x16[N_TOK * DMODEL];
__device__ __half g_c16[N_TOK * DMODEL];
__device__ __half g_wq16[DMODEL * DMODEL];   // transposed [N][K]
__device__ __half g_wk16[DMODEL * DMODEL];
__device__ __half g_wv16[DMODEL * DMODEL];
__device__ __half g_wo16[DMODEL * DMODEL];
__device__ __half g_q16[NHEAD * N_TOK * HD]; // head-major, pre-scaled
__device__ __half g_k16[NHEAD * N_TOK * HD];
__device__ __half g_vt16[DMODEL * N_TOK];    // V^T flat: [col][tok]

// ---------------- helpers ----------------------------------------------------
__device__ __forceinline__ void mma16816(float* d, const uint32_t* a, const uint32_t* b)
{
    asm volatile(
        "mma.sync.aligned.m16n8k16.row.col.f32.f16.f16.f32 "
        "{%0,%1,%2,%3}, {%4,%5,%6,%7}, {%8,%9}, {%0,%1,%2,%3};\n"
        : "+f"(d[0]), "+f"(d[1]), "+f"(d[2]), "+f"(d[3])
        : "r"(a[0]), "r"(a[1]), "r"(a[2]), "r"(a[3]), "r"(b[0]), "r"(b[1]));
}
__device__ __forceinline__ uint32_t pack_f16x2(float lo, float hi)
{
    uint32_t d;
    asm("cvt.rn.f16x2.f32 %0, %1, %2;" : "=r"(d) : "f"(hi), "f"(lo));
    return d;
}
__device__ __forceinline__ float fast_exp2(float x)
{
    float r;
    asm("ex2.approx.ftz.f32 %0, %1;" : "=f"(r) : "f"(x));
    return r;
}

// ---------------- conversion kernels -----------------------------------------
// x fp32 -> fp16 flat (8 elems/thread)
__global__ void __launch_bounds__(256) cvt_f16(const float* __restrict__ src,
                                               __half* __restrict__ dst)
{
    int i8 = (blockIdx.x * 256 + threadIdx.x) * 8;
    float4 a = *(const float4*)(src + i8);
    float4 b = *(const float4*)(src + i8 + 4);
    uint4 o;
    o.x = pack_f16x2(a.x, a.y);
    o.y = pack_f16x2(a.z, a.w);
    o.z = pack_f16x2(b.x, b.y);
    o.w = pack_f16x2(b.z, b.w);
    *(uint4*)(dst + i8) = o;
}

// All four W [K,N] fp32 -> Wt fp16 [N,K], z-indexed single launch
__global__ void __launch_bounds__(256) wT4_f16(
    const float* __restrict__ W0, const float* __restrict__ W1,
    const float* __restrict__ W2, const float* __restrict__ W3,
    __half* __restrict__ T0, __half* __restrict__ T1,
    __half* __restrict__ T2, __half* __restrict__ T3)
{
    const int z = blockIdx.z;
    const float* W = (z == 0) ? W0 : (z == 1) ? W1 : (z == 2) ? W2 : W3;
    __half* T = (z == 0) ? T0 : (z == 1) ? T1 : (z == 2) ? T2 : T3;

    __shared__ float t[32][33];
    const int bk = blockIdx.x * 32;
    const int bn = blockIdx.y * 32;
    const int x = threadIdx.x;
    const int y = threadIdx.y;
#pragma unroll
    for (int r = 0; r < 32; r += 8)
        t[y + r][x] = W[(size_t)(bk + y + r) * DMODEL + bn + x];
    __syncthreads();
#pragma unroll
    for (int r = 0; r < 32; r += 8)
        T[(size_t)(bn + y + r) * GK + bk + x] = __float2half_rn(t[x][y + r]);
}

// ---------------- fp16 mma GEMM core (shared by QKV + output proj) -----------
#define RSTRIDE 80
#define TILE_SM (128 * RSTRIDE)

// mainloop computes acc[4][4][4] for tile (bm, bn); A row-major [M,K], B [N,K]
#define GEMM_MAINLOOP(A, B)                                                        \
    float acc[4][4][4];                                                            \
    _Pragma("unroll")                                                              \
    for (int i = 0; i < 4; i++)                                                    \
        _Pragma("unroll")                                                          \
        for (int j = 0; j < 4; j++)                                                \
            _Pragma("unroll")                                                      \
            for (int v = 0; v < 4; v++) acc[i][j][v] = 0.0f;                       \
    uint4 pa[2], pb[2];                                                            \
    {                                                                              \
        const int kc = 0;                                                          \
        _Pragma("unroll")                                                          \
        for (int i = 0; i < 2; i++) {                                              \
            const int row = lrow + i * 64;                                         \
            pa[i] = *(const uint4*)((A) + (size_t)(bm + row) * GK + kc + lc * 8);  \
            pb[i] = *(const uint4*)((B) + (size_t)(bn + row) * GK + kc + lc * 8);  \
        }                                                                          \
    }                                                                              \
    for (int kci = 0; kci < GK / 32; kci++) {                                      \
        __syncthreads();                                                           \
        _Pragma("unroll")                                                          \
        for (int i = 0; i < 2; i++) {                                              \
            const uint32_t so = (uint32_t)(lrow + i * 64) * RSTRIDE + (uint32_t)lc * 16; \
            *(uint4*)(sA + so) = pa[i];                                            \
            *(uint4*)(sB + so) = pb[i];                                            \
        }                                                                          \
        __syncthreads();                                                           \
        if (kci + 1 < GK / 32) {                                                   \
            const int kc = (kci + 1) * 32;                                         \
            _Pragma("unroll")                                                      \
            for (int i = 0; i < 2; i++) {                                          \
                const int row = lrow + i * 64;                                     \
                pa[i] = *(const uint4*)((A) + (size_t)(bm + row) * GK + kc + lc * 8); \
                pb[i] = *(const uint4*)((B) + (size_t)(bn + row) * GK + kc + lc * 8); \
            }                                                                      \
        }                                                                          \
        _Pragma("unroll")                                                          \
        for (int k16 = 0; k16 < 2; k16++) {                                        \
            const int kb = k16 * 32;                                               \
            uint32_t bf[4][2];                                                     \
            _Pragma("unroll")                                                      \
            for (int na = 0; na < 4; na++) {                                       \
                const uint32_t nb = (uint32_t)(warp_n * 32 + na * 8 + qr) * RSTRIDE + kb + qk4; \
                bf[na][0] = *(const uint32_t*)(sB + nb);                           \
                bf[na][1] = *(const uint32_t*)(sB + nb + 16);                      \
            }                                                                      \
            _Pragma("unroll")                                                      \
            for (int ma = 0; ma < 4; ma++) {                                       \
                const uint32_t ab = (uint32_t)(warp_m * 64 + ma * 16 + qr) * RSTRIDE + kb + qk4; \
                uint32_t af[4];                                                    \
                af[0] = *(const uint32_t*)(sA + ab);                               \
                af[1] = *(const uint32_t*)(sA + ab + 8 * RSTRIDE);                 \
                af[2] = *(const uint32_t*)(sA + ab + 16);                          \
                af[3] = *(const uint32_t*)(sA + ab + 8 * RSTRIDE + 16);            \
                _Pragma("unroll")                                                  \
                for (int na = 0; na < 4; na++) mma16816(acc[ma][na], af, bf[na]);  \
            }                                                                      \
        }                                                                          \
    }

// Q/K/V projections in one launch: z=0 Q (scaled head-major), z=1 K, z=2 V^T
__global__ void __launch_bounds__(256) gemm_qkv(
    const __half* __restrict__ A,
    const __half* __restrict__ Bq, const __half* __restrict__ Bk,
    const __half* __restrict__ Bv,
    __half* __restrict__ q16, __half* __restrict__ k16,
    __half* __restrict__ vt16, float qscale)
{
    __shared__ __align__(16) char sA[TILE_SM];
    __shared__ __align__(16) char sB[TILE_SM];

    const int t = threadIdx.x;
    const int lane = t & 31;
    const int wid = t >> 5;
    const int warp_m = wid & 1;
    const int warp_n = wid >> 1;
    const int bm = blockIdx.y * 128;
    const int bn = blockIdx.x * 128;
    const int z = blockIdx.z;

    const int qr = lane >> 2;
    const int qk4 = (lane & 3) * 4;
    const int lrow = t >> 2;
    const int lc = t & 3;

    const __half* B = (z == 0) ? Bq : (z == 1) ? Bk : Bv;

    GEMM_MAINLOOP(A, B)

    if (z <= 1) {
        __half* dst = (z == 0) ? q16 : k16;
        const float scale = (z == 0) ? qscale : 1.0f;
#pragma unroll
        for (int ma = 0; ma < 4; ma++) {
            const int row0 = bm + warp_m * 64 + ma * 16 + qr;
#pragma unroll
            for (int na = 0; na < 4; na++) {
                const int col = bn + warp_n * 32 + na * 8 + (lane & 3) * 2;
                const int hh = col >> 6;
                const int d = col & 63;
                uint32_t p0 = pack_f16x2(acc[ma][na][0] * scale, acc[ma][na][1] * scale);
                uint32_t p1 = pack_f16x2(acc[ma][na][2] * scale, acc[ma][na][3] * scale);
                *(uint32_t*)(dst + ((size_t)hh * N_TOK + row0) * HD + d) = p0;
                *(uint32_t*)(dst + ((size_t)hh * N_TOK + row0 + 8) * HD + d) = p1;
            }
        }
    } else {
#pragma unroll
        for (int ma = 0; ma < 4; ma++) {
            const int row0 = bm + warp_m * 64 + ma * 16 + qr;
#pragma unroll
            for (int na = 0; na < 4; na++) {
                const int col = bn + warp_n * 32 + na * 8 + (lane & 3) * 2;
                vt16[(size_t)col * N_TOK + row0]           = __float2half_rn(acc[ma][na][0]);
                vt16[(size_t)(col + 1) * N_TOK + row0]     = __float2half_rn(acc[ma][na][1]);
                vt16[(size_t)col * N_TOK + row0 + 8]       = __float2half_rn(acc[ma][na][2]);
                vt16[(size_t)(col + 1) * N_TOK + row0 + 8] = __float2half_rn(acc[ma][na][3]);
            }
        }
    }
}

// Output projection: fp32 out + bias
__global__ void __launch_bounds__(256) gemm_out(
    const __half* __restrict__ A, const __half* __restrict__ B,
    const float* __restrict__ bias, float* __restrict__ Cf)
{
    __shared__ __align__(16) char sA[TILE_SM];
    __shared__ __align__(16) char sB[TILE_SM];

    const int t = threadIdx.x;
    const int lane = t & 31;
    const int wid = t >> 5;
    const int warp_m = wid & 1;
    const int warp_n = wid >> 1;
    const int bm = blockIdx.y * 128;
    const int bn = blockIdx.x * 128;

    const int qr = lane >> 2;
    const int qk4 = (lane & 3) * 4;
    const int lrow = t >> 2;
    const int lc = t & 3;

    GEMM_MAINLOOP(A, B)

#pragma unroll
    for (int ma = 0; ma < 4; ma++) {
        const int row0 = bm + warp_m * 64 + ma * 16 + qr;
#pragma unroll
        for (int na = 0; na < 4; na++) {
            const int col = bn + warp_n * 32 + na * 8 + (lane & 3) * 2;
            const float b0 = bias[col];
            const float b1 = bias[col + 1];
            float2 o0, o1;
            o0.x = acc[ma][na][0] + b0;
            o0.y = acc[ma][na][1] + b1;
            o1.x = acc[ma][na][2] + b0;
            o1.y = acc[ma][na][3] + b1;
            *(float2*)(Cf + (size_t)row0 * DMODEL + col) = o0;
            *(float2*)(Cf + (size_t)(row0 + 8) * DMODEL + col) = o1;
        }
    }
}

// ---------------- fp16 tensor-core causal flash attention --------------------
// CTA = (128 queries, 1 head), 256 threads, warp owns 16 rows.
// Register-prefetch pipelined K/V tile loads.
#define ASTRIDE 144
#define ATILE   (64 * ASTRIDE)

__global__ void __launch_bounds__(256) flash_f16(
    const __half* __restrict__ q16, const __half* __restrict__ k16,
    const __half* __restrict__ vt16,
    __half* __restrict__ C16)
{
    __shared__ __align__(16) char sK[ATILE];
    __shared__ __align__(16) char sV[ATILE];

    const int t = threadIdx.x;
    const int lane = t & 31;
    const int w = t >> 5;
    const int qb = 31 - blockIdx.x;        // heavy CTAs first
    const int h = blockIdx.y;
    const int qr = lane >> 2;
    const int qc = lane & 3;
    const int r0 = qb * 128 + w * 16 + qr;
    const int row_max = qb * 128 + w * 16 + 15;

    // per-thread load mapping (constant across blocks)
    const int lr0 = t >> 3;          // rows t/8 and t/8+32
    const int lcc = t & 7;

    uint4 pk[2], pv[2];
    auto gload = [&](int kb) {
        const size_t kgo = ((size_t)h * N_TOK + kb * 64) * HD;
        const size_t vco = (size_t)(h * HD) * N_TOK + kb * 64;
#pragma unroll
        for (int i = 0; i < 2; i++) {
            const int row = lr0 + i * 32;
            pk[i] = *(const uint4*)(k16 + kgo + (size_t)row * HD + lcc * 8);
            pv[i] = *(const uint4*)(vt16 + vco + (size_t)row * N_TOK + lcc * 8);
        }
    };

    // Q fragments, loaded once
    uint32_t qf[4][4];
    {
        const size_t base = ((size_t)h * N_TOK + r0) * HD;
#pragma unroll
        for (int ks = 0; ks < 4; ks++) {
            const int d0 = ks * 16 + 2 * qc;
            qf[ks][0] = *(const uint32_t*)(q16 + base + d0);
            qf[ks][1] = *(const uint32_t*)(q16 + base + 8 * HD + d0);
            qf[ks][2] = *(const uint32_t*)(q16 + base + d0 + 8);
            qf[ks][3] = *(const uint32_t*)(q16 + base + 8 * HD + d0 + 8);
        }
    }

    float o_[8][4];
#pragma unroll
    for (int na = 0; na < 8; na++)
#pragma unroll
        for (int j = 0; j < 4; j++) o_[na][j] = 0.0f;
    float m_[2] = {-1e30f, -1e30f};
    float l_[2] = {0.0f, 0.0f};

    const int kb_max = 2 * qb + 1;
    gload(0);

    for (int kb = 0; kb <= kb_max; kb++) {
        __syncthreads();   // previous block's fragment reads done
#pragma unroll
        for (int i = 0; i < 2; i++) {
            const uint32_t so = (uint32_t)(lr0 + i * 32) * ASTRIDE + (uint32_t)lcc * 16;
            *(uint4*)(sK + so) = pk[i];
            *(uint4*)(sV + so) = pv[i];
        }
        __syncthreads();
        if (kb < kb_max) gload(kb + 1);   // LDG latency hidden by compute below

        if (kb * 64 <= row_max) {
            // --- S = Q K^T ---
            float s_[8][4];
#pragma unroll
            for (int na = 0; na < 8; na++)
#pragma unroll
                for (int j = 0; j < 4; j++) s_[na][j] = 0.0f;

#pragma unroll
            for (int ks = 0; ks < 4; ks++) {
                uint32_t bf[8][2];
#pragma unroll
                for (int na = 0; na < 8; na++) {
                    const uint32_t a = (uint32_t)(na * 8 + qr) * ASTRIDE + ks * 32 + qc * 4;
                    bf[na][0] = *(const uint32_t*)(sK + a);
                    bf[na][1] = *(const uint32_t*)(sK + a + 16);
                }
#pragma unroll
                for (int na = 0; na < 8; na++) mma16816(s_[na], qf[ks], bf[na]);
            }

            // --- causal mask (diagonal blocks only) ---
            if (kb >= 2 * qb) {
#pragma unroll
                for (int na = 0; na < 8; na++) {
                    const int key0 = kb * 64 + na * 8 + 2 * qc;
                    if (key0 > r0)     s_[na][0] = -1e30f;
                    if (key0 + 1 > r0) s_[na][1] = -1e30f;
                    if (key0 > r0 + 8)     s_[na][2] = -1e30f;
                    if (key0 + 1 > r0 + 8) s_[na][3] = -1e30f;
                }
            }

            // --- online softmax (log2 domain; scale folded into Q) ---
            float corr[2];
#pragma unroll
            for (int r = 0; r < 2; r++) {
                float mx = -1e30f;
#pragma unroll
                for (int na = 0; na < 8; na++) {
                    mx = fmaxf(mx, s_[na][2 * r]);
                    mx = fmaxf(mx, s_[na][2 * r + 1]);
                }
                mx = fmaxf(mx, __shfl_xor_sync(0xffffffffu, mx, 1));
                mx = fmaxf(mx, __shfl_xor_sync(0xffffffffu, mx, 2));
                const float m_new = fmaxf(m_[r], mx);
                corr[r] = fast_exp2(m_[r] - m_new);
                m_[r] = m_new;
                float psum = 0.0f;
#pragma unroll
                for (int na = 0; na < 8; na++) {
                    float p0 = fast_exp2(s_[na][2 * r] - m_new);
                    float p1 = fast_exp2(s_[na][2 * r + 1] - m_new);
                    s_[na][2 * r] = p0;
                    s_[na][2 * r + 1] = p1;
                    psum += p0 + p1;
                }
                l_[r] = l_[r] * corr[r] + psum;
            }
#pragma unroll
            for (int na = 0; na < 8; na++) {
                o_[na][0] *= corr[0];
                o_[na][1] *= corr[0];
                o_[na][2] *= corr[1];
                o_[na][3] *= corr[1];
            }

            // --- P fragments (fp16), register-direct from S atoms ---
            uint32_t pafr[4][4];
#pragma unroll
            for (int ka = 0; ka < 4; ka++) {
                const float* pA = s_[2 * ka];
                const float* pB = s_[2 * ka + 1];
                pafr[ka][0] = pack_f16x2(pA[0], pA[1]);
                pafr[ka][1] = pack_f16x2(pA[2], pA[3]);
                pafr[ka][2] = pack_f16x2(pB[0], pB[1]);
                pafr[ka][3] = pack_f16x2(pB[2], pB[3]);
            }

            // --- O += P V ---
#pragma unroll
            for (int ka = 0; ka < 4; ka++) {
                uint32_t vf[8][2];
#pragma unroll
                for (int na = 0; na < 8; na++) {
                    const uint32_t a = (uint32_t)(na * 8 + qr) * ASTRIDE + ka * 32 + qc * 4;
                    vf[na][0] = *(const uint32_t*)(sV + a);
                    vf[na][1] = *(const uint32_t*)(sV + a + 16);
                }
#pragma unroll
                for (int na = 0; na < 8; na++) mma16816(o_[na], pafr[ka], vf[na]);
            }
        }
    }

    // finalize: quad-reduce l, normalize, store ctx as fp16
    float l0 = l_[0];
    l0 += __shfl_xor_sync(0xffffffffu, l0, 1);
    l0 += __shfl_xor_sync(0xffffffffu, l0, 2);
    float l1 = l_[1];
    l1 += __shfl_xor_sync(0xffffffffu, l1, 1);
    l1 += __shfl_xor_sync(0xffffffffu, l1, 2);
    const float inv0 = 1.0f / l0;
    const float inv1 = 1.0f / l1;

#pragma unroll
    for (int na = 0; na < 8; na++) {
        const int col = h * HD + na * 8 + 2 * qc;
        uint32_t p0 = pack_f16x2(o_[na][0] * inv0, o_[na][1] * inv0);
        uint32_t p1 = pack_f16x2(o_[na][2] * inv1, o_[na][3] * inv1);
        *(uint32_t*)(C16 + (size_t)r0 * DMODEL + col) = p0;
        *(uint32_t*)(C16 + (size_t)(r0 + 8) * DMODEL + col) = p1;
    }
}

// ---------------------------------------------------------------------------
extern "C" void kernel_launch(void* const* d_in, const int* in_sizes, int n_in,
                              void* d_out, int out_size)
{
    const float* x   = (const float*)d_in[0];
    const float* W_q = (const float*)d_in[1];
    const float* W_k = (const float*)d_in[2];
    const float* W_v = (const float*)d_in[3];
    const float* W_o = (const float*)d_in[4];
    const float* b_o = (const float*)d_in[5];
    float* out = (float*)d_out;

    __half *x16, *c16, *wq, *wk, *wv, *wo, *q16, *k16, *vt16;
    cudaGetSymbolAddress((void**)&x16, g_x16);
    cudaGetSymbolAddress((void**)&c16, g_c16);
    cudaGetSymbolAddress((void**)&wq, g_wq16);
    cudaGetSymbolAddress((void**)&wk, g_wk16);
    cudaGetSymbolAddress((void**)&wv, g_wv16);
    cudaGetSymbolAddress((void**)&wo, g_wo16);
    cudaGetSymbolAddress((void**)&q16, g_q16);
    cudaGetSymbolAddress((void**)&k16, g_k16);
    cudaGetSymbolAddress((void**)&vt16, g_vt16);

    // convert inputs to fp16 (2 launches total)
    cvt_f16<<<(N_TOK * DMODEL) / (256 * 8), 256>>>(x, x16);
    dim3 tgrid(DMODEL / 32, DMODEL / 32, 4);
    dim3 tblock(32, 8);
    wT4_f16<<<tgrid, tblock>>>(W_q, W_k, W_v, W_o, wq, wk, wv, wo);

    // Q/K/V projections in ONE launch (768 CTAs)
    const float qscale = 0.125f * 1.4426950408889634f;   // 1/sqrt(64) * log2(e)
    dim3 qkvgrid(DMODEL / 128, N_TOK / 128, 3);
    gemm_qkv<<<qkvgrid, 256>>>(x16, wq, wk, wv, q16, k16, vt16, qscale);

    // tensor-core causal flash attention (fp16, register-prefetch pipelined)
    dim3 agrid(N_TOK / 128, NHEAD);
    flash_f16<<<agrid, 256>>>(q16, k16, vt16, c16);

    // output projection: fp32 + bias to harness output
    dim3 ggrid(DMODEL / 128, N_TOK / 128);
    gemm_out<<<ggrid, 256>>>(c16, wo, b_o, out);
}